// round 15
// baseline (speedup 1.0000x reference)
#include <cuda_runtime.h>
#include <cuda_fp16.h>

#define H 512
#define W 512
#define OW 128
#define OH 8
#define NPK 66            // packs per row: halo cols 0..131, pack p = cols (2p, 2p+1)
#define NT 256

#define CEH(a, b) { __half2 _t = __hmin2(a, b); (b) = __hmax2(a, b); (a) = _t; }

__device__ __forceinline__ int reflect_idx(int i) {
    i = abs(i);
    return (i >= H) ? (2 * H - 2 - i) : i;
}

// optimal 5-sort, 9 CE (elementwise on half2 lanes)
__device__ __forceinline__ void sort5h(__half2& x0, __half2& x1, __half2& x2,
                                       __half2& x3, __half2& x4) {
    CEH(x0, x1); CEH(x3, x4); CEH(x2, x4); CEH(x2, x3); CEH(x0, x3);
    CEH(x0, x2); CEH(x1, x4); CEH(x1, x3); CEH(x1, x2);
}

__device__ __forceinline__ __half2 u2h(unsigned u) { return *reinterpret_cast<__half2*>(&u); }
__device__ __forceinline__ unsigned h2u(__half2 h) { return *reinterpret_cast<unsigned*>(&h); }

// median (7th smallest) of 13 staircase candidates (validated R4-R14).
// Final fold: med3(s5, L, s6) == max(s5, min(s6, L))  [s5 <= s6].
__device__ __forceinline__ __half2 sel13h(__half2 A, __half2 B, __half2 C, __half2 D,
                                          __half2 E, __half2 F, __half2 G, __half2 Hh,
                                          __half2 I, __half2 J, __half2 K, __half2 L,
                                          __half2 M) {
    CEH(A, C); CEH(E, Hh); CEH(C, E); CEH(B, D); CEH(B, C); CEH(D, E);
    CEH(F, I); CEH(K, M); CEH(I, K); CEH(G, J); CEH(G, I); CEH(J, K);
    __half2 s5 = __hmax2(__hmax2(__hmax2(__hmin2(A, M), __hmin2(B, K)),
                                 __hmax2(__hmin2(C, J), __hmin2(D, I))),
                         __hmax2(__hmin2(E, G), __hmin2(Hh, F)));
    __half2 s6 = __hmax2(__hmax2(__hmax2(A, __hmin2(B, M)),
                                 __hmax2(__hmin2(C, K), __hmin2(D, J))),
                         __hmax2(__hmax2(__hmin2(E, I), __hmin2(Hh, G)), F));
    return __hmax2(s5, __hmin2(s6, L));
}

__global__ __launch_bounds__(NT, 6) void median5x5_h4f_kernel(
    const float* __restrict__ in, float* __restrict__ out) {
    // sorted column packs: pack p holds halo columns (2p, 2p+1) as half2
    __shared__ unsigned scolp[OH][5][NPK];

    const int bx = blockIdx.x * OW;
    const int by = blockIdx.y * OH;
    const int plane = blockIdx.z;
    const float* src = in + (size_t)plane * (H * W);

    const int tid = threadIdx.x;
    const bool interior = (bx >= 2) & (bx + OW + 2 <= W) & (by >= 2) & (by + OH + 2 <= H);

    // Phase B (R8/R14): sort each column-pack over 5 adjacent rows.
    for (int k = tid; k < NPK * OH; k += NT) {
        int oy = k / NPK;
        int pp = k - oy * NPK;
        int sp = pp * 2;                        // even halo column
        __half2 v0, v1, v2, v3, v4;
        if (interior) {
            const float* p = src + (by + oy - 2) * W + (bx + sp - 2);   // 8B aligned
            v0 = __float22half2_rn(*(const float2*)(p));
            v1 = __float22half2_rn(*(const float2*)(p + W));
            v2 = __float22half2_rn(*(const float2*)(p + 2 * W));
            v3 = __float22half2_rn(*(const float2*)(p + 3 * W));
            v4 = __float22half2_rn(*(const float2*)(p + 4 * W));
        } else {
            int gx0 = reflect_idx(bx + sp - 2);
            int gx1 = reflect_idx(bx + sp - 1);
            int g0 = reflect_idx(by + oy - 2) * W;
            int g1 = reflect_idx(by + oy - 1) * W;
            int g2 = reflect_idx(by + oy + 0) * W;
            int g3 = reflect_idx(by + oy + 1) * W;
            int g4 = reflect_idx(by + oy + 2) * W;
            v0 = __floats2half2_rn(src[g0 + gx0], src[g0 + gx1]);
            v1 = __floats2half2_rn(src[g1 + gx0], src[g1 + gx1]);
            v2 = __floats2half2_rn(src[g2 + gx0], src[g2 + gx1]);
            v3 = __floats2half2_rn(src[g3 + gx0], src[g3 + gx1]);
            v4 = __floats2half2_rn(src[g4 + gx0], src[g4 + gx1]);
        }
        sort5h(v0, v1, v2, v3, v4);
        scolp[oy][0][pp] = h2u(v0);
        scolp[oy][1][pp] = h2u(v1);
        scolp[oy][2][pp] = h2u(v2);
        scolp[oy][3][pp] = h2u(v3);
        scolp[oy][4][pp] = h2u(v4);
    }
    __syncthreads();

    // Phase C: 4 adjacent pixels per thread = two half2 pairs.
    // Pair0 window = w0..w4, pair1 window = w2..w6; the shared middle triple
    // {w2,w3,w4} is processed ONCE per row, then each pair folds its two
    // private endpoints via exact two-list rank identities.
    const int oy = tid >> 5;
    const int xp = tid & 31;
    const int pbase = 2 * xp;

#define ROWPACKS(r, w0, w1, w2, w3, w4, w5, w6)                       \
    __half2 w0, w1, w2, w3, w4, w5, w6;                               \
    {   uint2 _q0 = *(const uint2*)&scolp[oy][r][pbase];              \
        uint2 _q1 = *(const uint2*)&scolp[oy][r][pbase + 2];          \
        w0 = u2h(_q0.x); w2 = u2h(_q0.y);                             \
        w4 = u2h(_q1.x); w6 = u2h(_q1.y);                             \
        w1 = u2h(__byte_perm(_q0.x, _q0.y, 0x5432));                  \
        w3 = u2h(__byte_perm(_q0.y, _q1.x, 0x5432));                  \
        w5 = u2h(__byte_perm(_q1.x, _q1.y, 0x5432)); }

    __half2 A0, B0, C0, D0, E0, F0, G0, H0, I0, J0, K0, L0, M0;
    __half2 A1, B1, C1, D1, E1, F1, G1, H1, I1, J1, K1, L1, M1;

    {   // row 0 (column minima): top2 -> A<=B (ranks 3,4)
        ROWPACKS(0, w0, w1, w2, w3, w4, w5, w6);
        __half2 a  = __hmin2(w2, w3), b = __hmax2(w2, w3);
        __half2 hi = __hmax2(b, w4);
        __half2 sec = __hmax2(a, __hmin2(b, w4));      // 2nd largest of triple
        {   __half2 p = __hmax2(w0, w1), q = __hmin2(w0, w1);
            B0 = __hmax2(hi, p);
            A0 = __hmax2(sec, __hmax2(q, __hmin2(hi, p))); }
        {   __half2 p = __hmax2(w5, w6), q = __hmin2(w5, w6);
            B1 = __hmax2(hi, p);
            A1 = __hmax2(sec, __hmax2(q, __hmin2(hi, p))); }
    }
    {   // row 1: top3 -> C<=D<=E (ranks 2,3,4)
        ROWPACKS(1, w0, w1, w2, w3, w4, w5, w6);
        CEH(w2, w3); CEH(w3, w4); CEH(w2, w3);         // s0=w2 <= s1=w3 <= s2=w4
        {   __half2 p = __hmax2(w0, w1), q = __hmin2(w0, w1);
            E0 = __hmax2(w4, p);
            D0 = __hmax2(__hmax2(w3, q), __hmin2(w4, p));
            C0 = __hmax2(__hmax2(w2, __hmin2(w3, p)), __hmin2(w4, q)); }
        {   __half2 p = __hmax2(w5, w6), q = __hmin2(w5, w6);
            E1 = __hmax2(w4, p);
            D1 = __hmax2(__hmax2(w3, q), __hmin2(w4, p));
            C1 = __hmax2(__hmax2(w2, __hmin2(w3, p)), __hmin2(w4, q)); }
    }
    {   // row 2: mid3 -> F<=G<=H (ranks 1,2,3)
        ROWPACKS(2, w0, w1, w2, w3, w4, w5, w6);
        CEH(w2, w3); CEH(w3, w4); CEH(w2, w3);         // s0<=s1<=s2
        {   __half2 p = __hmax2(w0, w1), q = __hmin2(w0, w1);
            __half2 t = __hmin2(w3, p), m = __hmax2(w2, q);
            F0 = __hmin2(t, m);
            G0 = __hmax2(__hmax2(w2, t), __hmin2(w4, q));
            H0 = __hmax2(__hmax2(w3, q), __hmin2(w4, p)); }
        {   __half2 p = __hmax2(w5, w6), q = __hmin2(w5, w6);
            __half2 t = __hmin2(w3, p), m = __hmax2(w2, q);
            F1 = __hmin2(t, m);
            G1 = __hmax2(__hmax2(w2, t), __hmin2(w4, q));
            H1 = __hmax2(__hmax2(w3, q), __hmin2(w4, p)); }
    }
    {   // row 3: bot3 -> I<=J<=K (ranks 0,1,2)
        ROWPACKS(3, w0, w1, w2, w3, w4, w5, w6);
        CEH(w2, w3); CEH(w3, w4); CEH(w2, w3);         // s0<=s1<=s2
        {   __half2 p = __hmax2(w0, w1), q = __hmin2(w0, w1);
            I0 = __hmin2(w2, q);
            J0 = __hmin2(__hmin2(w3, p), __hmax2(w2, q));
            K0 = __hmin2(w4, __hmin2(__hmax2(w3, q), __hmax2(w2, p))); }
        {   __half2 p = __hmax2(w5, w6), q = __hmin2(w5, w6);
            I1 = __hmin2(w2, q);
            J1 = __hmin2(__hmin2(w3, p), __hmax2(w2, q));
            K1 = __hmin2(w4, __hmin2(__hmax2(w3, q), __hmax2(w2, p))); }
    }
    {   // row 4 (column maxima): bot2 -> L<=M (ranks 0,1)
        ROWPACKS(4, w0, w1, w2, w3, w4, w5, w6);
        __half2 a  = __hmin2(w2, w3), b = __hmax2(w2, w3);
        __half2 lo  = __hmin2(a, w4);
        __half2 slo = __hmin2(b, __hmax2(a, w4));      // 2nd smallest of triple
        {   __half2 p = __hmax2(w0, w1), q = __hmin2(w0, w1);
            L0 = __hmin2(lo, q);
            M0 = __hmin2(slo, __hmin2(p, __hmax2(lo, q))); }
        {   __half2 p = __hmax2(w5, w6), q = __hmin2(w5, w6);
            L1 = __hmin2(lo, q);
            M1 = __hmin2(slo, __hmin2(p, __hmax2(lo, q))); }
    }

    __half2 med0 = sel13h(A0, B0, C0, D0, E0, F0, G0, H0, I0, J0, K0, L0, M0);
    __half2 med1 = sel13h(A1, B1, C1, D1, E1, F1, G1, H1, I1, J1, K1, L1, M1);

    float4 o;
    o.x = __low2float(med0);
    o.y = __high2float(med0);
    o.z = __low2float(med1);
    o.w = __high2float(med1);
    *(float4*)(out + (size_t)plane * (H * W) + (by + oy) * W + (bx + 4 * xp)) = o;
#undef ROWPACKS
}

extern "C" void kernel_launch(void* const* d_in, const int* in_sizes, int n_in,
                              void* d_out, int out_size) {
    const float* img = (const float*)d_in[0];
    float* out = (float*)d_out;
    int planes = in_sizes[0] / (H * W);   // 4 * 3 = 12

    dim3 block(NT);
    dim3 grid(W / OW, H / OH, planes);   // (4, 64, 12) = 3072 blocks
    median5x5_h4f_kernel<<<grid, block>>>(img, out);
}

// round 16
// speedup vs baseline: 1.0122x; 1.0122x over previous
#include <cuda_runtime.h>
#include <cuda_fp16.h>

#define H 512
#define W 512
#define OW 128
#define OH 8
#define NPK 66            // packs per row: halo cols 0..131, pack p = cols (2p, 2p+1)
#define NT 256

#define CEH(a, b) { __half2 _t = __hmin2(a, b); (b) = __hmax2(a, b); (a) = _t; }

__device__ __forceinline__ int reflect_idx(int i) {
    i = abs(i);
    return (i >= H) ? (2 * H - 2 - i) : i;
}

// optimal 5-sort, 9 CE (elementwise on half2 lanes)
__device__ __forceinline__ void sort5h(__half2& x0, __half2& x1, __half2& x2,
                                       __half2& x3, __half2& x4) {
    CEH(x0, x1); CEH(x3, x4); CEH(x2, x4); CEH(x2, x3); CEH(x0, x3);
    CEH(x0, x2); CEH(x1, x4); CEH(x1, x3); CEH(x1, x2);
}

__device__ __forceinline__ __half2 u2h(unsigned u) { return *reinterpret_cast<__half2*>(&u); }
__device__ __forceinline__ unsigned h2u(__half2 h) { return *reinterpret_cast<unsigned*>(&h); }

// median (7th smallest) of the 13 staircase candidates — poset-aware v2.
// Row chains: A<=B; C<=D<=E; F<=G<=H; I<=J<=K; L<=M.
// Col chains: A<=D<=H; B<=E; C<=G<=K; F<=J<=M; I<=L.
// P5 = sorted{A,B,D,E,H}; Q5 = sorted{F,I,J,L,M}; T3 = (C,G,K) already sorted.
// R8 = oddeven-merge(P5, T3); median = rank6 of R8 ∪ Q5 (verified by hand x2).
__device__ __forceinline__ __half2 sel13h(__half2 A, __half2 B, __half2 C, __half2 D,
                                          __half2 E, __half2 F, __half2 G, __half2 Hh,
                                          __half2 I, __half2 J, __half2 K, __half2 L,
                                          __half2 M) {
    // P5 = (A, d0, m2, m3, h1)
    __half2 d0 = __hmin2(B, D), d1 = __hmax2(B, D);
    __half2 h0 = __hmin2(E, Hh), h1 = __hmax2(E, Hh);
    __half2 m2 = __hmin2(d1, h0), m3 = __hmax2(d1, h0);
    // Q5 = (a, q1, q2, q3, M)   [b = max(F,I) <= J]
    __half2 a  = __hmin2(F, I), b = __hmax2(F, I);
    __half2 jl0 = __hmin2(J, L), q3 = __hmax2(J, L);
    __half2 q1 = __hmin2(b, L);
    __half2 q2 = __hmax2(b, jl0);
    // merge P5 with T3=(C,G,K): evens (A,m2,h1)+(C,K), odds (d0,m3)+(G)
    // r0 (=min) and r7 (=max) of R8 are unused by rank6 -> dropped.
    __half2 w  = __hmax2(A, C);
    __half2 t1 = __hmin2(w, h1), t2 = __hmax2(w, h1);
    __half2 u0 = __hmin2(m2, K), u1 = __hmax2(m2, K);
    __half2 e1 = __hmin2(t1, u0), e2 = __hmax2(t1, u0);
    __half2 e3 = __hmin2(t2, u1);
    __half2 o0 = __hmin2(d0, G), v2 = __hmax2(d0, G);
    __half2 o1 = __hmin2(v2, m3), o2 = __hmax2(v2, m3);
    __half2 r1 = __hmin2(e1, o0), r2 = __hmax2(e1, o0);
    __half2 r3 = __hmin2(e2, o1), r4 = __hmax2(e2, o1);
    __half2 r5 = __hmin2(e3, o2), r6 = __hmax2(e3, o2);
    // rank6 of R8 ∪ Q5: max(R1, min(R2,q4), min(R3,q3), min(R4,q2), min(R5,q1), min(R6,q0))
    return __hmax2(__hmax2(__hmax2(r1, __hmin2(r2, M)),
                           __hmax2(__hmin2(r3, q3), __hmin2(r4, q2))),
                   __hmax2(__hmin2(r5, q1), __hmin2(r6, a)));
}

__global__ __launch_bounds__(NT, 6) void median5x5_h4g_kernel(
    const float* __restrict__ in, float* __restrict__ out) {
    // sorted column packs: pack p holds halo columns (2p, 2p+1) as half2
    __shared__ unsigned scolp[OH][5][NPK];

    const int bx = blockIdx.x * OW;
    const int by = blockIdx.y * OH;
    const int plane = blockIdx.z;
    const float* src = in + (size_t)plane * (H * W);

    const int tid = threadIdx.x;
    const bool interior = (bx >= 2) & (bx + OW + 2 <= W) & (by >= 2) & (by + OH + 2 <= H);

    // Phase B: one item = a PAIR of adjacent packs (4 halo cols). 264 items:
    // shared addressing, STS.64 per rank, ~1 iteration per thread.
    for (int k = tid; k < 33 * OH; k += NT) {
        int oy = k / 33;
        int q  = k - oy * 33;
        int sp = q * 4;                      // halo col base of packs 2q, 2q+1
        __half2 va0, va1, va2, va3, va4, vb0, vb1, vb2, vb3, vb4;
        if (interior) {
            const float* p = src + (by + oy - 2) * W + (bx + sp - 2);   // 8B aligned
            va0 = __float22half2_rn(*(const float2*)(p));
            vb0 = __float22half2_rn(*(const float2*)(p + 2));
            va1 = __float22half2_rn(*(const float2*)(p + W));
            vb1 = __float22half2_rn(*(const float2*)(p + W + 2));
            va2 = __float22half2_rn(*(const float2*)(p + 2 * W));
            vb2 = __float22half2_rn(*(const float2*)(p + 2 * W + 2));
            va3 = __float22half2_rn(*(const float2*)(p + 3 * W));
            vb3 = __float22half2_rn(*(const float2*)(p + 3 * W + 2));
            va4 = __float22half2_rn(*(const float2*)(p + 4 * W));
            vb4 = __float22half2_rn(*(const float2*)(p + 4 * W + 2));
        } else {
            int gx0 = reflect_idx(bx + sp - 2);
            int gx1 = reflect_idx(bx + sp - 1);
            int gx2 = reflect_idx(bx + sp + 0);
            int gx3 = reflect_idx(bx + sp + 1);
            int g0 = reflect_idx(by + oy - 2) * W;
            int g1 = reflect_idx(by + oy - 1) * W;
            int g2 = reflect_idx(by + oy + 0) * W;
            int g3 = reflect_idx(by + oy + 1) * W;
            int g4 = reflect_idx(by + oy + 2) * W;
            va0 = __floats2half2_rn(src[g0 + gx0], src[g0 + gx1]);
            vb0 = __floats2half2_rn(src[g0 + gx2], src[g0 + gx3]);
            va1 = __floats2half2_rn(src[g1 + gx0], src[g1 + gx1]);
            vb1 = __floats2half2_rn(src[g1 + gx2], src[g1 + gx3]);
            va2 = __floats2half2_rn(src[g2 + gx0], src[g2 + gx1]);
            vb2 = __floats2half2_rn(src[g2 + gx2], src[g2 + gx3]);
            va3 = __floats2half2_rn(src[g3 + gx0], src[g3 + gx1]);
            vb3 = __floats2half2_rn(src[g3 + gx2], src[g3 + gx3]);
            va4 = __floats2half2_rn(src[g4 + gx0], src[g4 + gx1]);
            vb4 = __floats2half2_rn(src[g4 + gx2], src[g4 + gx3]);
        }
        sort5h(va0, va1, va2, va3, va4);
        sort5h(vb0, vb1, vb2, vb3, vb4);
        *(uint2*)&scolp[oy][0][2 * q] = make_uint2(h2u(va0), h2u(vb0));
        *(uint2*)&scolp[oy][1][2 * q] = make_uint2(h2u(va1), h2u(vb1));
        *(uint2*)&scolp[oy][2][2 * q] = make_uint2(h2u(va2), h2u(vb2));
        *(uint2*)&scolp[oy][3][2 * q] = make_uint2(h2u(va3), h2u(vb3));
        *(uint2*)&scolp[oy][4][2 * q] = make_uint2(h2u(va4), h2u(vb4));
    }
    __syncthreads();

    // Phase C (R15, unchanged): 4 adjacent pixels per thread = two half2
    // pairs; shared middle-triple stats + per-pair endpoint folds.
    const int oy = tid >> 5;
    const int xp = tid & 31;
    const int pbase = 2 * xp;

#define ROWPACKS(r, w0, w1, w2, w3, w4, w5, w6)                       \
    __half2 w0, w1, w2, w3, w4, w5, w6;                               \
    {   uint2 _q0 = *(const uint2*)&scolp[oy][r][pbase];              \
        uint2 _q1 = *(const uint2*)&scolp[oy][r][pbase + 2];          \
        w0 = u2h(_q0.x); w2 = u2h(_q0.y);                             \
        w4 = u2h(_q1.x); w6 = u2h(_q1.y);                             \
        w1 = u2h(__byte_perm(_q0.x, _q0.y, 0x5432));                  \
        w3 = u2h(__byte_perm(_q0.y, _q1.x, 0x5432));                  \
        w5 = u2h(__byte_perm(_q1.x, _q1.y, 0x5432)); }

    __half2 A0, B0, C0, D0, E0, F0, G0, H0, I0, J0, K0, L0, M0;
    __half2 A1, B1, C1, D1, E1, F1, G1, H1, I1, J1, K1, L1, M1;

    {   // row 0 (column minima): top2 -> A<=B (ranks 3,4)
        ROWPACKS(0, w0, w1, w2, w3, w4, w5, w6);
        __half2 a  = __hmin2(w2, w3), b = __hmax2(w2, w3);
        __half2 hi = __hmax2(b, w4);
        __half2 sec = __hmax2(a, __hmin2(b, w4));
        {   __half2 p = __hmax2(w0, w1), q = __hmin2(w0, w1);
            B0 = __hmax2(hi, p);
            A0 = __hmax2(sec, __hmax2(q, __hmin2(hi, p))); }
        {   __half2 p = __hmax2(w5, w6), q = __hmin2(w5, w6);
            B1 = __hmax2(hi, p);
            A1 = __hmax2(sec, __hmax2(q, __hmin2(hi, p))); }
    }
    {   // row 1: top3 -> C<=D<=E (ranks 2,3,4)
        ROWPACKS(1, w0, w1, w2, w3, w4, w5, w6);
        CEH(w2, w3); CEH(w3, w4); CEH(w2, w3);         // s0<=s1<=s2
        {   __half2 p = __hmax2(w0, w1), q = __hmin2(w0, w1);
            E0 = __hmax2(w4, p);
            D0 = __hmax2(__hmax2(w3, q), __hmin2(w4, p));
            C0 = __hmax2(__hmax2(w2, __hmin2(w3, p)), __hmin2(w4, q)); }
        {   __half2 p = __hmax2(w5, w6), q = __hmin2(w5, w6);
            E1 = __hmax2(w4, p);
            D1 = __hmax2(__hmax2(w3, q), __hmin2(w4, p));
            C1 = __hmax2(__hmax2(w2, __hmin2(w3, p)), __hmin2(w4, q)); }
    }
    {   // row 2: mid3 -> F<=G<=H (ranks 1,2,3)
        ROWPACKS(2, w0, w1, w2, w3, w4, w5, w6);
        CEH(w2, w3); CEH(w3, w4); CEH(w2, w3);         // s0<=s1<=s2
        {   __half2 p = __hmax2(w0, w1), q = __hmin2(w0, w1);
            __half2 t = __hmin2(w3, p), m = __hmax2(w2, q);
            F0 = __hmin2(t, m);
            G0 = __hmax2(__hmax2(w2, t), __hmin2(w4, q));
            H0 = __hmax2(__hmax2(w3, q), __hmin2(w4, p)); }
        {   __half2 p = __hmax2(w5, w6), q = __hmin2(w5, w6);
            __half2 t = __hmin2(w3, p), m = __hmax2(w2, q);
            F1 = __hmin2(t, m);
            G1 = __hmax2(__hmax2(w2, t), __hmin2(w4, q));
            H1 = __hmax2(__hmax2(w3, q), __hmin2(w4, p)); }
    }
    {   // row 3: bot3 -> I<=J<=K (ranks 0,1,2)
        ROWPACKS(3, w0, w1, w2, w3, w4, w5, w6);
        CEH(w2, w3); CEH(w3, w4); CEH(w2, w3);         // s0<=s1<=s2
        {   __half2 p = __hmax2(w0, w1), q = __hmin2(w0, w1);
            I0 = __hmin2(w2, q);
            J0 = __hmin2(__hmin2(w3, p), __hmax2(w2, q));
            K0 = __hmin2(w4, __hmin2(__hmax2(w3, q), __hmax2(w2, p))); }
        {   __half2 p = __hmax2(w5, w6), q = __hmin2(w5, w6);
            I1 = __hmin2(w2, q);
            J1 = __hmin2(__hmin2(w3, p), __hmax2(w2, q));
            K1 = __hmin2(w4, __hmin2(__hmax2(w3, q), __hmax2(w2, p))); }
    }
    {   // row 4 (column maxima): bot2 -> L<=M (ranks 0,1)
        ROWPACKS(4, w0, w1, w2, w3, w4, w5, w6);
        __half2 a  = __hmin2(w2, w3), b = __hmax2(w2, w3);
        __half2 lo  = __hmin2(a, w4);
        __half2 slo = __hmin2(b, __hmax2(a, w4));
        {   __half2 p = __hmax2(w0, w1), q = __hmin2(w0, w1);
            L0 = __hmin2(lo, q);
            M0 = __hmin2(slo, __hmin2(p, __hmax2(lo, q))); }
        {   __half2 p = __hmax2(w5, w6), q = __hmin2(w5, w6);
            L1 = __hmin2(lo, q);
            M1 = __hmin2(slo, __hmin2(p, __hmax2(lo, q))); }
    }

    __half2 med0 = sel13h(A0, B0, C0, D0, E0, F0, G0, H0, I0, J0, K0, L0, M0);
    __half2 med1 = sel13h(A1, B1, C1, D1, E1, F1, G1, H1, I1, J1, K1, L1, M1);

    float4 o;
    o.x = __low2float(med0);
    o.y = __high2float(med0);
    o.z = __low2float(med1);
    o.w = __high2float(med1);
    *(float4*)(out + (size_t)plane * (H * W) + (by + oy) * W + (bx + 4 * xp)) = o;
#undef ROWPACKS
}

extern "C" void kernel_launch(void* const* d_in, const int* in_sizes, int n_in,
                              void* d_out, int out_size) {
    const float* img = (const float*)d_in[0];
    float* out = (float*)d_out;
    int planes = in_sizes[0] / (H * W);   // 4 * 3 = 12

    dim3 block(NT);
    dim3 grid(W / OW, H / OH, planes);   // (4, 64, 12) = 3072 blocks
    median5x5_h4g_kernel<<<grid, block>>>(img, out);
}

// round 17
// speedup vs baseline: 1.1013x; 1.0880x over previous
#include <cuda_runtime.h>
#include <cuda_fp16.h>

#define H 512
#define W 512
#define OW 128
#define OH 8
#define NPK 66            // packs per row: halo cols 0..131, pack p = cols (2p, 2p+1)
#define NT 256

#define CEH(a, b) { __half2 _t = __hmin2(a, b); (b) = __hmax2(a, b); (a) = _t; }

__device__ __forceinline__ int reflect_idx(int i) {
    i = abs(i);
    return (i >= H) ? (2 * H - 2 - i) : i;
}

__device__ __forceinline__ __half2 u2h(unsigned u) { return *reinterpret_cast<__half2*>(&u); }
__device__ __forceinline__ unsigned h2u(__half2 h) { return *reinterpret_cast<unsigned*>(&h); }

// median (7th smallest) of the 13 staircase candidates — poset-aware v2
// (field-verified bit-identical in R16).
__device__ __forceinline__ __half2 sel13h(__half2 A, __half2 B, __half2 C, __half2 D,
                                          __half2 E, __half2 F, __half2 G, __half2 Hh,
                                          __half2 I, __half2 J, __half2 K, __half2 L,
                                          __half2 M) {
    __half2 d0 = __hmin2(B, D), d1 = __hmax2(B, D);
    __half2 h0 = __hmin2(E, Hh), h1 = __hmax2(E, Hh);
    __half2 m2 = __hmin2(d1, h0), m3 = __hmax2(d1, h0);
    __half2 a  = __hmin2(F, I), b = __hmax2(F, I);
    __half2 jl0 = __hmin2(J, L), q3 = __hmax2(J, L);
    __half2 q1 = __hmin2(b, L);
    __half2 q2 = __hmax2(b, jl0);
    __half2 w  = __hmax2(A, C);
    __half2 t1 = __hmin2(w, h1), t2 = __hmax2(w, h1);
    __half2 u0 = __hmin2(m2, K), u1 = __hmax2(m2, K);
    __half2 e1 = __hmin2(t1, u0), e2 = __hmax2(t1, u0);
    __half2 e3 = __hmin2(t2, u1);
    __half2 o0 = __hmin2(d0, G), v2 = __hmax2(d0, G);
    __half2 o1 = __hmin2(v2, m3), o2 = __hmax2(v2, m3);
    __half2 r1 = __hmin2(e1, o0), r2 = __hmax2(e1, o0);
    __half2 r3 = __hmin2(e2, o1), r4 = __hmax2(e2, o1);
    __half2 r5 = __hmin2(e3, o2), r6 = __hmax2(e3, o2);
    return __hmax2(__hmax2(__hmax2(r1, __hmin2(r2, M)),
                           __hmax2(__hmin2(r3, q3), __hmin2(r4, q2))),
                   __hmax2(__hmin2(r5, q1), __hmin2(r6, a)));
}

__global__ __launch_bounds__(NT, 6) void median5x5_h4h_kernel(
    const float* __restrict__ in, float* __restrict__ out) {
    // sorted column packs: pack p holds halo columns (2p, 2p+1) as half2
    __shared__ unsigned scolp[OH][5][NPK];

    const int bx = blockIdx.x * OW;
    const int by = blockIdx.y * OH;
    const int plane = blockIdx.z;
    const float* src = in + (size_t)plane * (H * W);

    const int tid = threadIdx.x;
    const bool interior = (bx >= 2) & (bx + OW + 2 <= W) & (by >= 2) & (by + OH + 2 <= H);

    // Phase B with VERTICAL SHARING: one item = (oy-pair g, pack pp).
    // Columns oy=2g (rows 2g-2..2g+2) and oy=2g+1 (rows 2g-1..2g+3) share the
    // 4-row core 2g-1..2g+2: sort4 once, sorted-insert each endpoint.
    // 264 items, ~1 per thread (vs 528 sort5 items before).
    for (int k = tid; k < 4 * NPK; k += NT) {
        int g  = k / NPK;                    // oy pair: rows 2g, 2g+1
        int pp = k - g * NPK;
        int sp = pp * 2;                     // even halo column
        __half2 v0, v1, v2, v3, v4, v5;      // rows 2g-2 .. 2g+3
        if (interior) {
            const float* p = src + (by + 2 * g - 2) * W + (bx + sp - 2);   // 8B aligned
            v0 = __float22half2_rn(*(const float2*)(p));
            v1 = __float22half2_rn(*(const float2*)(p + W));
            v2 = __float22half2_rn(*(const float2*)(p + 2 * W));
            v3 = __float22half2_rn(*(const float2*)(p + 3 * W));
            v4 = __float22half2_rn(*(const float2*)(p + 4 * W));
            v5 = __float22half2_rn(*(const float2*)(p + 5 * W));
        } else {
            int gx0 = reflect_idx(bx + sp - 2);
            int gx1 = reflect_idx(bx + sp - 1);
            int g0 = reflect_idx(by + 2 * g - 2) * W;
            int g1 = reflect_idx(by + 2 * g - 1) * W;
            int g2 = reflect_idx(by + 2 * g + 0) * W;
            int g3 = reflect_idx(by + 2 * g + 1) * W;
            int g4 = reflect_idx(by + 2 * g + 2) * W;
            int g5 = reflect_idx(by + 2 * g + 3) * W;
            v0 = __floats2half2_rn(src[g0 + gx0], src[g0 + gx1]);
            v1 = __floats2half2_rn(src[g1 + gx0], src[g1 + gx1]);
            v2 = __floats2half2_rn(src[g2 + gx0], src[g2 + gx1]);
            v3 = __floats2half2_rn(src[g3 + gx0], src[g3 + gx1]);
            v4 = __floats2half2_rn(src[g4 + gx0], src[g4 + gx1]);
            v5 = __floats2half2_rn(src[g5 + gx0], src[g5 + gx1]);
        }
        // sort4 of core rows v1..v4 (5 CE)
        CEH(v1, v2); CEH(v3, v4); CEH(v1, v3); CEH(v2, v4); CEH(v2, v3);
        // column oy=2g: insert v0 into sorted (v1,v2,v3,v4)
        scolp[2 * g][0][pp] = h2u(__hmin2(v1, v0));
        scolp[2 * g][1][pp] = h2u(__hmax2(v1, __hmin2(v2, v0)));
        scolp[2 * g][2][pp] = h2u(__hmax2(v2, __hmin2(v3, v0)));
        scolp[2 * g][3][pp] = h2u(__hmax2(v3, __hmin2(v4, v0)));
        scolp[2 * g][4][pp] = h2u(__hmax2(v4, v0));
        // column oy=2g+1: insert v5 into sorted (v1,v2,v3,v4)
        scolp[2 * g + 1][0][pp] = h2u(__hmin2(v1, v5));
        scolp[2 * g + 1][1][pp] = h2u(__hmax2(v1, __hmin2(v2, v5)));
        scolp[2 * g + 1][2][pp] = h2u(__hmax2(v2, __hmin2(v3, v5)));
        scolp[2 * g + 1][3][pp] = h2u(__hmax2(v3, __hmin2(v4, v5)));
        scolp[2 * g + 1][4][pp] = h2u(__hmax2(v4, v5));
    }
    __syncthreads();

    // Phase C (R15, unchanged): 4 adjacent pixels per thread = two half2
    // pairs; shared middle-triple stats + per-pair endpoint folds.
    const int oy = tid >> 5;
    const int xp = tid & 31;
    const int pbase = 2 * xp;

#define ROWPACKS(r, w0, w1, w2, w3, w4, w5, w6)                       \
    __half2 w0, w1, w2, w3, w4, w5, w6;                               \
    {   uint2 _q0 = *(const uint2*)&scolp[oy][r][pbase];              \
        uint2 _q1 = *(const uint2*)&scolp[oy][r][pbase + 2];          \
        w0 = u2h(_q0.x); w2 = u2h(_q0.y);                             \
        w4 = u2h(_q1.x); w6 = u2h(_q1.y);                             \
        w1 = u2h(__byte_perm(_q0.x, _q0.y, 0x5432));                  \
        w3 = u2h(__byte_perm(_q0.y, _q1.x, 0x5432));                  \
        w5 = u2h(__byte_perm(_q1.x, _q1.y, 0x5432)); }

    __half2 A0, B0, C0, D0, E0, F0, G0, H0, I0, J0, K0, L0, M0;
    __half2 A1, B1, C1, D1, E1, F1, G1, H1, I1, J1, K1, L1, M1;

    {   // row 0 (column minima): top2 -> A<=B (ranks 3,4)
        ROWPACKS(0, w0, w1, w2, w3, w4, w5, w6);
        __half2 a  = __hmin2(w2, w3), b = __hmax2(w2, w3);
        __half2 hi = __hmax2(b, w4);
        __half2 sec = __hmax2(a, __hmin2(b, w4));
        {   __half2 p = __hmax2(w0, w1), q = __hmin2(w0, w1);
            B0 = __hmax2(hi, p);
            A0 = __hmax2(sec, __hmax2(q, __hmin2(hi, p))); }
        {   __half2 p = __hmax2(w5, w6), q = __hmin2(w5, w6);
            B1 = __hmax2(hi, p);
            A1 = __hmax2(sec, __hmax2(q, __hmin2(hi, p))); }
    }
    {   // row 1: top3 -> C<=D<=E (ranks 2,3,4)
        ROWPACKS(1, w0, w1, w2, w3, w4, w5, w6);
        CEH(w2, w3); CEH(w3, w4); CEH(w2, w3);
        {   __half2 p = __hmax2(w0, w1), q = __hmin2(w0, w1);
            E0 = __hmax2(w4, p);
            D0 = __hmax2(__hmax2(w3, q), __hmin2(w4, p));
            C0 = __hmax2(__hmax2(w2, __hmin2(w3, p)), __hmin2(w4, q)); }
        {   __half2 p = __hmax2(w5, w6), q = __hmin2(w5, w6);
            E1 = __hmax2(w4, p);
            D1 = __hmax2(__hmax2(w3, q), __hmin2(w4, p));
            C1 = __hmax2(__hmax2(w2, __hmin2(w3, p)), __hmin2(w4, q)); }
    }
    {   // row 2: mid3 -> F<=G<=H (ranks 1,2,3)
        ROWPACKS(2, w0, w1, w2, w3, w4, w5, w6);
        CEH(w2, w3); CEH(w3, w4); CEH(w2, w3);
        {   __half2 p = __hmax2(w0, w1), q = __hmin2(w0, w1);
            __half2 t = __hmin2(w3, p), m = __hmax2(w2, q);
            F0 = __hmin2(t, m);
            G0 = __hmax2(__hmax2(w2, t), __hmin2(w4, q));
            H0 = __hmax2(__hmax2(w3, q), __hmin2(w4, p)); }
        {   __half2 p = __hmax2(w5, w6), q = __hmin2(w5, w6);
            __half2 t = __hmin2(w3, p), m = __hmax2(w2, q);
            F1 = __hmin2(t, m);
            G1 = __hmax2(__hmax2(w2, t), __hmin2(w4, q));
            H1 = __hmax2(__hmax2(w3, q), __hmin2(w4, p)); }
    }
    {   // row 3: bot3 -> I<=J<=K (ranks 0,1,2)
        ROWPACKS(3, w0, w1, w2, w3, w4, w5, w6);
        CEH(w2, w3); CEH(w3, w4); CEH(w2, w3);
        {   __half2 p = __hmax2(w0, w1), q = __hmin2(w0, w1);
            I0 = __hmin2(w2, q);
            J0 = __hmin2(__hmin2(w3, p), __hmax2(w2, q));
            K0 = __hmin2(w4, __hmin2(__hmax2(w3, q), __hmax2(w2, p))); }
        {   __half2 p = __hmax2(w5, w6), q = __hmin2(w5, w6);
            I1 = __hmin2(w2, q);
            J1 = __hmin2(__hmin2(w3, p), __hmax2(w2, q));
            K1 = __hmin2(w4, __hmin2(__hmax2(w3, q), __hmax2(w2, p))); }
    }
    {   // row 4 (column maxima): bot2 -> L<=M (ranks 0,1)
        ROWPACKS(4, w0, w1, w2, w3, w4, w5, w6);
        __half2 a  = __hmin2(w2, w3), b = __hmax2(w2, w3);
        __half2 lo  = __hmin2(a, w4);
        __half2 slo = __hmin2(b, __hmax2(a, w4));
        {   __half2 p = __hmax2(w0, w1), q = __hmin2(w0, w1);
            L0 = __hmin2(lo, q);
            M0 = __hmin2(slo, __hmin2(p, __hmax2(lo, q))); }
        {   __half2 p = __hmax2(w5, w6), q = __hmin2(w5, w6);
            L1 = __hmin2(lo, q);
            M1 = __hmin2(slo, __hmin2(p, __hmax2(lo, q))); }
    }

    __half2 med0 = sel13h(A0, B0, C0, D0, E0, F0, G0, H0, I0, J0, K0, L0, M0);
    __half2 med1 = sel13h(A1, B1, C1, D1, E1, F1, G1, H1, I1, J1, K1, L1, M1);

    float4 o;
    o.x = __low2float(med0);
    o.y = __high2float(med0);
    o.z = __low2float(med1);
    o.w = __high2float(med1);
    *(float4*)(out + (size_t)plane * (H * W) + (by + oy) * W + (bx + 4 * xp)) = o;
#undef ROWPACKS
}

extern "C" void kernel_launch(void* const* d_in, const int* in_sizes, int n_in,
                              void* d_out, int out_size) {
    const float* img = (const float*)d_in[0];
    float* out = (float*)d_out;
    int planes = in_sizes[0] / (H * W);   // 4 * 3 = 12

    dim3 block(NT);
    dim3 grid(W / OW, H / OH, planes);   // (4, 64, 12) = 3072 blocks
    median5x5_h4h_kernel<<<grid, block>>>(img, out);
}